// round 17
// baseline (speedup 1.0000x reference)
#include <cuda_runtime.h>
#include <cuda_fp16.h>

// Bilinear flow warp. input1: [B,C,H,W] fp32, flow: [B,2,H,W] fp32.
// Fixed shapes: B=8, C=64, H=256, W=448.
//
// Pass A: NCHW fp32 -> NHWC fp16 scratch; STG.128 packed writeback.
// Pass B: 4-corner gather (corner = 64 contiguous fp16 ch = 128B), MLP=8
//         batched LDGs, uint4 weight/offset broadcast LDS, half2 FMA blend,
//         cw-major fp16 result tile, STG.128 NCHW fp32 writeback.
// Serial monolithic launches (all split/overlap schedules measured slower).

#define B_   8
#define C_   64
#define H_   256
#define W_   448
#define HW_  (H_ * W_)            // 114688
#define CHW_ (C_ * HW_)           // 7340032
#define TILES_PER_B (HW_ / 64)    // 1792 (W=448 divisible by 64: tile stays in one row)

// ~117 MB scratch: input in NHWC fp16 layout [B, H, W, C]
__device__ static __half g_nhwc[(size_t)B_ * HW_ * C_];

static __device__ __forceinline__ unsigned int h2bits(__half2 h) {
    return *(unsigned int*)&h;
}
static __device__ __forceinline__ __half2 bits2h(unsigned int u) {
    return *(__half2*)&u;
}

// ---------------------------------------------------------------------------
// Kernel A: NCHW fp32 -> NHWC fp16.  Tile = 64 ch x 64 px, 256 threads.
// ---------------------------------------------------------------------------
__global__ void __launch_bounds__(256) nchw_to_nhwc_f16(const float* __restrict__ in)
{
    __shared__ float sm[64 * 65];    // [c][px], row stride 65

    int blk  = blockIdx.x;
    int b    = blk / TILES_PER_B;
    int tile = blk - b * TILES_PER_B;
    int px0  = tile * 64;
    int tid  = threadIdx.x;

    // ---- load: float4 per thread (16 threads cover one channel row of 64 px) ----
    {
        int c_lo = tid >> 4;             // 0..15
        int px4  = (tid & 15) * 4;       // 0..60
        const float* src = in + b * CHW_ + px0 + px4;
        #pragma unroll
        for (int it = 0; it < 4; ++it) {
            int c = it * 16 + c_lo;
            float4 v = *(const float4*)(src + c * HW_);
            float* s = sm + c * 65 + px4;
            s[0] = v.x; s[1] = v.y; s[2] = v.z; s[3] = v.w;
        }
    }
    __syncthreads();

    // ---- store: 512 uint4 items (64 px x 8 groups of 8 channels); 2/thread.
    //      item -> (px, g): channels 8g..8g+7 at pixel px -> one STG.128.
    //      Warp covers 512B contiguous. ----
    {
        uint4* dst = (uint4*)(g_nhwc + (size_t)(b * HW_ + px0) * 64);
        #pragma unroll
        for (int k = 0; k < 2; ++k) {
            int idx = k * 256 + tid;
            int px  = idx >> 3;          // 0..63
            int g   = idx & 7;           // 0..7 -> channels 8g..8g+7
            const float* col = sm + (8 * g) * 65 + px;
            uint4 u;
            u.x = h2bits(__floats2half2_rn(col[0 * 65], col[1 * 65]));
            u.y = h2bits(__floats2half2_rn(col[2 * 65], col[3 * 65]));
            u.z = h2bits(__floats2half2_rn(col[4 * 65], col[5 * 65]));
            u.w = h2bits(__floats2half2_rn(col[6 * 65], col[7 * 65]));
            dst[px * 8 + g] = u;
        }
    }
}

// ---------------------------------------------------------------------------
// Kernel B: gather from NHWC fp16, write NCHW fp32.
// Block = 256 threads handles 64 consecutive pixels (one row) x 64 channels.
// ---------------------------------------------------------------------------
__global__ void __launch_bounds__(256, 8) warp_gather_f16(
    const float* __restrict__ flow,   // [B,2,H,W]
    float* __restrict__ out)          // [B,C,H,W]
{
    __shared__ alignas(16) __half2 s_wh[64][4];  // per-pixel corner weights (half2-bcast)
    __shared__ alignas(16) int     s_o[64][4];   // per-pixel corner base offsets (half idx)
    __shared__ __half2 s_r[32 * 65];             // result tile [cw][px], stride 65

    int blk  = blockIdx.x;
    int b    = blk / TILES_PER_B;
    int tile = blk - b * TILES_PER_B;
    int rem0 = tile * 64;
    int tid  = threadIdx.x;

    // ---- phase 1: ONE thread per pixel; all 4 corners; 2x STS.128 ----
    if (tid < 64) {
        int px  = tid;
        int rem = rem0 + px;
        int h   = rem / W_;
        int w   = rem - h * W_;

        const float* fl = flow + b * 2 * HW_ + rem;
        float fx = __ldg(fl);
        float fy = __ldg(fl + HW_);

        float x = (float)w + fx;
        float y = (float)h + fy;

        float x0f = floorf(x);
        float y0f = floorf(y);
        int x0 = (int)x0f;
        int y0 = (int)y0f;
        int x1 = x0 + 1;
        int y1 = y0 + 1;

        float wx1 = x - x0f;
        float wx0 = 1.0f - wx1;
        float wy1 = y - y0f;
        float wy0 = 1.0f - wy1;

        float vx0 = (x0 >= 0 && x0 < W_) ? 1.0f : 0.0f;
        float vx1 = (x1 >= 0 && x1 < W_) ? 1.0f : 0.0f;
        float vy0 = (y0 >= 0 && y0 < H_) ? 1.0f : 0.0f;
        float vy1 = (y1 >= 0 && y1 < H_) ? 1.0f : 0.0f;

        int x0c = min(max(x0, 0), W_ - 1);
        int x1c = min(max(x1, 0), W_ - 1);
        int y0c = min(max(y0, 0), H_ - 1);
        int y1c = min(max(y1, 0), H_ - 1);

        uint4 wq;
        wq.x = h2bits(__float2half2_rn(wy0 * wx0 * vy0 * vx0));
        wq.y = h2bits(__float2half2_rn(wy0 * wx1 * vy0 * vx1));
        wq.z = h2bits(__float2half2_rn(wy1 * wx0 * vy1 * vx0));
        wq.w = h2bits(__float2half2_rn(wy1 * wx1 * vy1 * vx1));

        int row0 = (b * H_ + y0c) * W_;
        int row1 = (b * H_ + y1c) * W_;
        uint4 oq;
        oq.x = (unsigned int)((row0 + x0c) * 64);
        oq.y = (unsigned int)((row0 + x1c) * 64);
        oq.z = (unsigned int)((row1 + x0c) * 64);
        oq.w = (unsigned int)((row1 + x1c) * 64);

        *(uint4*)(&s_wh[px][0]) = wq;
        *(uint4*)(&s_o[px][0])  = oq;
    }
    __syncthreads();

    // ---- phase 2: 8 warps x 8 pixels; lane covers channels (2*lane, 2*lane+1).
    //      MLP=8 (2 px x 4 corners), uint4 offset/weight broadcast loads,
    //      half2 blend, cw-major STS (banks (lane+p)%32: conflict-free). ----
    {
        int wid  = tid >> 5;
        int lane = tid & 31;

        #pragma unroll
        for (int hblk = 0; hblk < 4; ++hblk) {
            int pbase = wid * 8 + hblk * 2;

            __half2 v[2][4];
            #pragma unroll
            for (int j = 0; j < 2; ++j) {
                uint4 ov = *(const uint4*)(&s_o[pbase + j][0]);   // 1 LDS.128 (bcast)
                v[j][0] = __ldg((const __half2*)(g_nhwc + (int)ov.x) + lane);
                v[j][1] = __ldg((const __half2*)(g_nhwc + (int)ov.y) + lane);
                v[j][2] = __ldg((const __half2*)(g_nhwc + (int)ov.z) + lane);
                v[j][3] = __ldg((const __half2*)(g_nhwc + (int)ov.w) + lane);
            }

            #pragma unroll
            for (int j = 0; j < 2; ++j) {
                int p = pbase + j;
                uint4 wv = *(const uint4*)(&s_wh[p][0]);          // 1 LDS.128 (bcast)
                __half2 r = __hfma2(v[j][0], bits2h(wv.x),
                            __hfma2(v[j][1], bits2h(wv.y),
                            __hfma2(v[j][2], bits2h(wv.z),
                            __hmul2(v[j][3], bits2h(wv.w)))));
                s_r[lane * 65 + p] = r;
            }
        }
    }
    __syncthreads();

    // ---- phase 3: STG.128 NCHW fp32 writeback.
    //      Thread (cw = tid>>3, q = tid&7) handles channels (2cw, 2cw+1),
    //      pixels 8q..8q+7: 8 LDS.32 + 4 STG.128. Warp instr covers 4
    //      channels x 128B contiguous px runs. ----
    {
        int cw = tid >> 3;               // 0..31
        int q  = tid & 7;                // 0..7
        const __half2* src = s_r + cw * 65 + 8 * q;

        float lo[8], hi[8];
        #pragma unroll
        for (int i = 0; i < 8; ++i) {
            float2 f = __half22float2(src[i]);
            lo[i] = f.x;                 // channel 2cw   @ px 8q+i
            hi[i] = f.y;                 // channel 2cw+1 @ px 8q+i
        }

        float* dst = out + b * CHW_ + rem0 + 8 * q;
        float* d0 = dst + (2 * cw) * HW_;
        float* d1 = dst + (2 * cw + 1) * HW_;
        *(float4*)(d0)     = make_float4(lo[0], lo[1], lo[2], lo[3]);
        *(float4*)(d0 + 4) = make_float4(lo[4], lo[5], lo[6], lo[7]);
        *(float4*)(d1)     = make_float4(hi[0], hi[1], hi[2], hi[3]);
        *(float4*)(d1 + 4) = make_float4(hi[4], hi[5], hi[6], hi[7]);
    }
}

extern "C" void kernel_launch(void* const* d_in, const int* in_sizes, int n_in,
                              void* d_out, int out_size)
{
    const float* img  = (const float*)d_in[0];
    const float* flow = (const float*)d_in[1];
    float* out = (float*)d_out;

    const int blocks = B_ * TILES_PER_B;   // 14336
    nchw_to_nhwc_f16<<<blocks, 256>>>(img);
    warp_gather_f16<<<blocks, 256>>>(flow, out);
}